// round 6
// baseline (speedup 1.0000x reference)
#include <cuda_runtime.h>
#include <stdint.h>

#define NB   16384
#define FDIM 2048
#define HID  256
#define NODES 9
#define NSD  2304   // 9*256

// ---------------- static scratch ----------------
__device__ float g_ns0[(size_t)NB * NSD];
__device__ float g_ns1[(size_t)NB * NSD];
__device__ float g_agg[(size_t)NB * NSD];
__device__ float g_ct [(size_t)NB * FDIM];   // tf32-rounded conc
__device__ float g_wt [(size_t)NSD * FDIM];  // tf32-rounded f2n_w
__device__ float g_wc [HID * 512];           // folded step weight (tf32-rounded)
__device__ float g_bc [HID];                 // folded step bias (fp32)

// ---------------- helpers ----------------
__device__ __forceinline__ float f2t(float x){
    uint32_t u; asm("cvt.rna.tf32.f32 %0, %1;" : "=r"(u) : "f"(x));
    return __uint_as_float(u);
}
__device__ __forceinline__ float4 f2t4(float4 v){
    v.x=f2t(v.x); v.y=f2t(v.y); v.z=f2t(v.z); v.w=f2t(v.w); return v;
}
__device__ __forceinline__ float4 f4add(float4 a, float4 b){
    a.x+=b.x; a.y+=b.y; a.z+=b.z; a.w+=b.w; return a;
}
__device__ __forceinline__ float4 f4sub(float4 a, float4 b){
    a.x-=b.x; a.y-=b.y; a.z-=b.z; a.w-=b.w; return a;
}
__device__ __forceinline__ float4 f4scale(float4 a, float s){
    a.x*=s; a.y*=s; a.z*=s; a.w*=s; return a;
}
__device__ __forceinline__ uint32_t smem_u32(const void* p){
    uint32_t a;
    asm("{ .reg .u64 t; cvta.to.shared.u64 t, %1; cvt.u32.u64 %0, t; }" : "=r"(a) : "l"(p));
    return a;
}
__device__ __forceinline__ void mma8(float c[4], const uint32_t a[4], uint32_t b0, uint32_t b1){
    asm volatile(
        "mma.sync.aligned.m16n8k8.row.col.f32.tf32.tf32.f32 "
        "{%0,%1,%2,%3},{%4,%5,%6,%7},{%8,%9},{%0,%1,%2,%3};\n"
        : "+f"(c[0]),"+f"(c[1]),"+f"(c[2]),"+f"(c[3])
        : "r"(a[0]),"r"(a[1]),"r"(a[2]),"r"(a[3]),"r"(b0),"r"(b1));
}
#define LDSM4(r0,r1,r2,r3,addr) \
    asm volatile("ldmatrix.sync.aligned.m8n8.x4.shared.b16 {%0,%1,%2,%3}, [%4];" \
        : "=r"(r0),"=r"(r1),"=r"(r2),"=r"(r3) : "r"(addr))

#define CP16(dst, src) asm volatile("cp.async.cg.shared.global [%0], [%1], 16;\n" :: "r"(dst), "l"(src))
#define CP_COMMIT()    asm volatile("cp.async.commit_group;\n" ::: "memory")
#define CP_WAIT1()     asm volatile("cp.async.wait_group 1;\n" ::: "memory")

// ---------------- weight folding ----------------
__global__ void prep_k(const float* __restrict__ msgw, const float* __restrict__ msgb,
                       const float* __restrict__ updw, const float* __restrict__ updb){
    int o = blockIdx.x, t = threadIdx.x;
    __shared__ float u2[HID];
    u2[t] = updw[o*512 + 256 + t];
    __syncthreads();
    g_wc[o*512 + t] = f2t(updw[o*512 + t]);
    float s = 0.f;
    #pragma unroll 8
    for (int j = 0; j < HID; j++) s += u2[j] * msgw[j*HID + t];
    g_wc[o*512 + 256 + t] = f2t(s);
    if (t == 0){
        float sb = 0.f;
        for (int j = 0; j < HID; j++) sb += u2[j] * msgb[j];
        g_bc[o] = updb[o] + sb;
    }
}

// ---------------- tf32 pre-rounding of GEMM inputs ----------------
__global__ void round_conc_k(const float* __restrict__ src){
    size_t i = (size_t)blockIdx.x*256 + threadIdx.x;
    ((float4*)g_ct)[i] = f2t4(((const float4*)src)[i]);
}
__global__ void round_w_k(const float* __restrict__ src){
    size_t i = (size_t)blockIdx.x*256 + threadIdx.x;
    ((float4*)g_wt)[i] = f2t4(((const float4*)src)[i]);
}

// ---------------- adjacency aggregation (writes tf32-rounded) ----------------
__global__ void __launch_bounds__(256) agg_k(int sel){
    const float* __restrict__ src = sel ? g_ns1 : g_ns0;
    int idx = blockIdx.x*256 + threadIdx.x;           // over NB*64
    int b = idx >> 6, h4 = (idx & 63) << 2;
    const float* base = src + (size_t)b*NSD + h4;
    float4 v[9];
    #pragma unroll
    for (int j = 0; j < 9; j++) v[j] = *(const float4*)(base + j*HID);
    float4 sall = v[0];
    #pragma unroll
    for (int j = 1; j < 9; j++) sall = f4add(sall, v[j]);
    float* ob = g_agg + (size_t)b*NSD + h4;
    *(float4*)(ob + 0*HID) = f2t4(f4scale(sall, 1.f/9.f));
    *(float4*)(ob + 1*HID) = f2t4(f4scale(f4add(v[0], v[1]), 0.5f));
    float4 b06 = f4add(v[0], f4add(v[7], v[8]));
    #pragma unroll
    for (int i = 2; i <= 6; i++)
        *(float4*)(ob + i*HID) = f2t4(f4scale(f4add(b06, v[i]), 0.25f));
    float4 r78 = f2t4(f4scale(f4sub(sall, v[1]), 0.125f));
    *(float4*)(ob + 7*HID) = r78;
    *(float4*)(ob + 8*HID) = r78;
}

// ---------------- tf32 mma.sync GEMM, cutlass-sm80 style ----------------
// CTA tile 128(M) x 256(N), K chunks of 32. 8 warps, warp tile 64x64.
// 3-stage cp.async ring, ldmatrix.x4 fragment loads, fused epilogue.
// MODE 0: g_ct[16384,2048] @ g_wt[2304,2048]^T + init epilogue -> g_ns0
// MODE 1: [ns|agg][147456,512] @ g_wc[256,512]^T, tanh epilogue -> ns ping-pong
#define PADROW 144                 // 36 floats per 32-float k-row (LDSM conflict-free)
#define AS_BYTES (128*PADROW)      // 18432
#define STAGE_BYTES (AS_BYTES + 256*PADROW)   // 55296
template<int MODE>
__global__ void __launch_bounds__(256, 1) gemm_k(
    const float* __restrict__ f2nb, const float* __restrict__ logits,
    const float* __restrict__ encw, const float* __restrict__ encb,
    int sel)
{
    constexpr int KB = (MODE==0) ? FDIM : 512;
    constexpr int NC = KB / 32;

    extern __shared__ char smem_raw[];
    const uint32_t sbase = smem_u32(smem_raw);

    const int tid = threadIdx.x, wid = tid >> 5, lane = tid & 31;
    const int row0 = blockIdx.y * 128, col0 = blockIdx.x * 256;

    // ---- global load mapping ----
    const int arow = tid >> 1, aseg0 = (tid & 1) * 4;   // A: 128 rows, 2 threads/row
    const int brow = tid;                               // B: 256 rows, 1 thread/row
    const uint32_t adst0 = (uint32_t)arow*PADROW + (uint32_t)aseg0*16;
    const uint32_t bdst0 = AS_BYTES + (uint32_t)brow*PADROW;

    const float* agp; const float* agp2 = nullptr; const float* bgp;
    if constexpr (MODE == 0){
        agp = g_ct + (size_t)(row0 + arow)*FDIM + aseg0*4;
        bgp = g_wt + (size_t)(col0 + brow)*FDIM;
    } else {
        int r = row0 + arow, b = r / 9, n = r - 9*b;
        size_t base = (size_t)b*NSD + n*HID + aseg0*4;
        agp  = (sel ? g_ns1 : g_ns0) + base;
        agp2 = g_agg + base;
        bgp  = g_wc + (size_t)brow*KB;      // col0 == 0 in MODE 1
    }

    auto load_stage = [&](int s, int c){
        const uint32_t sb = sbase + (uint32_t)s*STAGE_BYTES;
        const float* ap;
        if constexpr (MODE == 0) ap = agp + c*32;
        else                     ap = ((c < 8) ? agp : agp2) + (c & 7)*32;
        const float* bp = bgp + c*32;
        #pragma unroll
        for (int j = 0; j < 4; j++) CP16(sb + adst0 + j*16, ap + 4*j);
        #pragma unroll
        for (int j = 0; j < 8; j++) CP16(sb + bdst0 + j*16, bp + 4*j);
        CP_COMMIT();
    };

    // ---- fragment (ldmatrix) address setup ----
    const int mb = (wid & 1) * 64, nb = (wid >> 1) * 64;
    const int sub = lane >> 3;
    const int lrf = (sub & 1)*8 + (lane & 7);      // A: row within 16-row tile
    const int lca = (sub >> 1) * 16;               // A: 16B chunk (k 0-3 / 4-7)
    uint32_t aoff[4];
    #pragma unroll
    for (int fm = 0; fm < 4; fm++)
        aoff[fm] = (uint32_t)(mb + fm*16 + lrf)*PADROW + lca;
    const int brf = (sub >> 1)*8 + (lane & 7);     // B: row within 16-row pair
    const int lcb = (sub & 1) * 16;
    uint32_t boff[4];
    #pragma unroll
    for (int p = 0; p < 4; p++)
        boff[p] = AS_BYTES + (uint32_t)(nb + p*16 + brf)*PADROW + lcb;

    float acc[4][8][4];
    #pragma unroll
    for (int i=0;i<4;i++)
        #pragma unroll
        for (int j=0;j<8;j++)
            #pragma unroll
            for (int e=0;e<4;e++) acc[i][j][e] = 0.f;

    // ---- prologue: 2 stages in flight ----
    load_stage(0, 0);
    load_stage(1, 1);

    // ---- main loop ----
    for (int c = 0; c < NC; c++){
        CP_WAIT1();                 // chunk c landed
        __syncthreads();            // all warps done with stage (c-1)%3 == (c+2)%3
        if (c + 2 < NC) load_stage((c + 2) % 3, c + 2);
        else            CP_COMMIT();

        const uint32_t stg = sbase + (uint32_t)(c % 3)*STAGE_BYTES;
        #pragma unroll
        for (int ks = 0; ks < 4; ks++){
            uint32_t a[4][4], b[8][2];
            #pragma unroll
            for (int fm = 0; fm < 4; fm++)
                LDSM4(a[fm][0], a[fm][1], a[fm][2], a[fm][3], stg + aoff[fm] + ks*32);
            #pragma unroll
            for (int p = 0; p < 4; p++)
                LDSM4(b[2*p][0], b[2*p][1], b[2*p+1][0], b[2*p+1][1], stg + boff[p] + ks*32);
            #pragma unroll
            for (int fm = 0; fm < 4; fm++)
                #pragma unroll
                for (int fn = 0; fn < 8; fn++)
                    mma8(acc[fm][fn], a[fm], b[fn][0], b[fn][1]);
        }
    }

    // ---- fused epilogue (register accumulators) ----
    const int g = lane >> 2, tg = lane & 3;
    #pragma unroll
    for (int fm = 0; fm < 4; fm++){
        const int gm = row0 + mb + fm*16 + g;
        size_t cb0, cb1;
        float lg0 = 0.f, lg1 = 0.f;
        if constexpr (MODE == 0){
            const int node = col0 >> 8;            // 256-col tile = exactly one node
            lg0 = logits[gm*9 + node];
            lg1 = logits[(gm+8)*9 + node];
            cb0 = (size_t)gm * NSD;
            cb1 = (size_t)(gm + 8) * NSD;
        } else {
            const int g2 = gm + 8;
            cb0 = (size_t)(gm/9)*NSD + (gm%9)*HID;
            cb1 = (size_t)(g2/9)*NSD + (g2%9)*HID;
        }
        float* dst0; float* dst1;
        if constexpr (MODE == 0){ dst0 = g_ns0 + cb0; dst1 = g_ns0 + cb1; }
        else { float* d = sel ? g_ns0 : g_ns1; dst0 = d + cb0; dst1 = d + cb1; }

        #pragma unroll
        for (int fn = 0; fn < 8; fn++){
            const int gn = col0 + nb + fn*8 + 2*tg;
            float2 v0, v1;
            if constexpr (MODE == 0){
                const int h = gn & 255;
                const float a0 = f2nb[gn]   + encb[h];
                const float a1 = f2nb[gn+1] + encb[h+1];
                const float e0 = encw[h], e1 = encw[h+1];
                v0.x = f2t(acc[fm][fn][0] + a0 + lg0*e0);
                v0.y = f2t(acc[fm][fn][1] + a1 + lg0*e1);
                v1.x = f2t(acc[fm][fn][2] + a0 + lg1*e0);
                v1.y = f2t(acc[fm][fn][3] + a1 + lg1*e1);
            } else {
                const float b0 = g_bc[gn], b1 = g_bc[gn+1];
                v0.x = f2t(tanhf(acc[fm][fn][0] + b0));
                v0.y = f2t(tanhf(acc[fm][fn][1] + b1));
                v1.x = f2t(tanhf(acc[fm][fn][2] + b0));
                v1.y = f2t(tanhf(acc[fm][fn][3] + b1));
            }
            *(float2*)(dst0 + gn) = v0;
            *(float2*)(dst1 + gn) = v1;
        }
    }
}

// ---------------- output heads ----------------
__global__ void __launch_bounds__(256) out_k(const float* __restrict__ outw,
                                             const float* __restrict__ outb,
                                             float* __restrict__ out){
    int wid = threadIdx.x >> 5, lane = threadIdx.x & 31;
    int b = blockIdx.x * 8 + wid;
    const float* r7 = g_ns0 + (size_t)b*NSD + 7*HID;
    float s7 = 0.f, s8 = 0.f;
    #pragma unroll
    for (int i = lane; i < HID; i += 32){
        float w = outw[i];
        s7 += r7[i] * w;
        s8 += r7[i + HID] * w;
    }
    #pragma unroll
    for (int o = 16; o > 0; o >>= 1){
        s7 += __shfl_xor_sync(0xffffffffu, s7, o);
        s8 += __shfl_xor_sync(0xffffffffu, s8, o);
    }
    if (lane == 0){
        out[b]      = s7 + outb[0];
        out[NB + b] = s8 + outb[0];
    }
}

// ---------------- launch ----------------
extern "C" void kernel_launch(void* const* d_in, const int* in_sizes, int n_in,
                              void* d_out, int out_size){
    const float* conc   = (const float*)d_in[0];
    const float* logits = (const float*)d_in[1];
    const float* encw   = (const float*)d_in[2];
    const float* encb   = (const float*)d_in[3];
    const float* f2nw   = (const float*)d_in[4];
    const float* f2nb   = (const float*)d_in[5];
    const float* msgw   = (const float*)d_in[6];
    const float* msgb   = (const float*)d_in[7];
    const float* updw   = (const float*)d_in[8];
    const float* updb   = (const float*)d_in[9];
    const float* outw   = (const float*)d_in[10];
    const float* outb   = (const float*)d_in[11];
    float* out = (float*)d_out;

    const int SMEM_BYTES = 3 * STAGE_BYTES;   // 165888
    cudaFuncSetAttribute(gemm_k<0>, cudaFuncAttributeMaxDynamicSharedMemorySize, SMEM_BYTES);
    cudaFuncSetAttribute(gemm_k<1>, cudaFuncAttributeMaxDynamicSharedMemorySize, SMEM_BYTES);

    prep_k<<<256, 256>>>(msgw, msgb, updw, updb);
    round_conc_k<<<(NB*(FDIM/4))/256, 256>>>(conc);
    round_w_k<<<(NSD*(FDIM/4))/256, 256>>>(f2nw);

    // init: node_states -> g_ns0
    gemm_k<0><<<dim3(NSD/256, NB/128), 256, SMEM_BYTES>>>(f2nb, logits, encw, encb, 0);

    // 4 message-passing steps (folded single-GEMM form, ping-pong ns0/ns1)
    for (int s = 0; s < 4; s++){
        agg_k<<<(NB*64)/256, 256>>>(s & 1);
        gemm_k<1><<<dim3(1, (NB*NODES)/128), 256, SMEM_BYTES>>>(nullptr, nullptr,
                                                                nullptr, nullptr, s & 1);
    }

    out_k<<<NB/8, 256>>>(outw, outb, out);
}

// round 8
// speedup vs baseline: 1.1270x; 1.1270x over previous
#include <cuda_runtime.h>
#include <stdint.h>

#define NB   16384
#define FDIM 2048
#define HID  256
#define NODES 9
#define NSD  2304   // 9*256

// ---------------- static scratch ----------------
__device__ float g_ns0[(size_t)NB * NSD];
__device__ float g_ns1[(size_t)NB * NSD];
__device__ float g_agg[(size_t)NB * NSD];
__device__ float g_ct [(size_t)NB * FDIM];   // tf32-rounded conc
__device__ float g_wt [(size_t)NSD * FDIM];  // tf32-rounded f2n_w
__device__ float g_wc [HID * 512];           // folded step weight (tf32-rounded)
__device__ float g_bc [HID];                 // folded step bias (fp32)

// ---------------- helpers ----------------
__device__ __forceinline__ float f2t(float x){
    uint32_t u; asm("cvt.rna.tf32.f32 %0, %1;" : "=r"(u) : "f"(x));
    return __uint_as_float(u);
}
__device__ __forceinline__ float4 f2t4(float4 v){
    v.x=f2t(v.x); v.y=f2t(v.y); v.z=f2t(v.z); v.w=f2t(v.w); return v;
}
__device__ __forceinline__ float4 f4add(float4 a, float4 b){
    a.x+=b.x; a.y+=b.y; a.z+=b.z; a.w+=b.w; return a;
}
__device__ __forceinline__ float4 f4sub(float4 a, float4 b){
    a.x-=b.x; a.y-=b.y; a.z-=b.z; a.w-=b.w; return a;
}
__device__ __forceinline__ float4 f4scale(float4 a, float s){
    a.x*=s; a.y*=s; a.z*=s; a.w*=s; return a;
}
__device__ __forceinline__ uint32_t smem_u32(const void* p){
    uint32_t a;
    asm("{ .reg .u64 t; cvta.to.shared.u64 t, %1; cvt.u32.u64 %0, t; }" : "=r"(a) : "l"(p));
    return a;
}
__device__ __forceinline__ void mma8(float c[4], const uint32_t a[4], uint32_t b0, uint32_t b1){
    asm volatile(
        "mma.sync.aligned.m16n8k8.row.col.f32.tf32.tf32.f32 "
        "{%0,%1,%2,%3},{%4,%5,%6,%7},{%8,%9},{%0,%1,%2,%3};\n"
        : "+f"(c[0]),"+f"(c[1]),"+f"(c[2]),"+f"(c[3])
        : "r"(a[0]),"r"(a[1]),"r"(a[2]),"r"(a[3]),"r"(b0),"r"(b1));
}
#define LDSM4(r0,r1,r2,r3,addr) \
    asm volatile("ldmatrix.sync.aligned.m8n8.x4.shared.b16 {%0,%1,%2,%3}, [%4];" \
        : "=r"(r0),"=r"(r1),"=r"(r2),"=r"(r3) : "r"(addr))

#define CP16(dst, src) asm volatile("cp.async.cg.shared.global [%0], [%1], 16;\n" :: "r"(dst), "l"(src))
#define CP_COMMIT()    asm volatile("cp.async.commit_group;\n" ::: "memory")
#define CP_WAIT1()     asm volatile("cp.async.wait_group 1;\n" ::: "memory")

// ---------------- weight folding ----------------
__global__ void prep_k(const float* __restrict__ msgw, const float* __restrict__ msgb,
                       const float* __restrict__ updw, const float* __restrict__ updb){
    int o = blockIdx.x, t = threadIdx.x;
    __shared__ float u2[HID];
    u2[t] = updw[o*512 + 256 + t];
    __syncthreads();
    g_wc[o*512 + t] = f2t(updw[o*512 + t]);
    float s = 0.f;
    #pragma unroll 8
    for (int j = 0; j < HID; j++) s += u2[j] * msgw[j*HID + t];
    g_wc[o*512 + 256 + t] = f2t(s);
    if (t == 0){
        float sb = 0.f;
        for (int j = 0; j < HID; j++) sb += u2[j] * msgb[j];
        g_bc[o] = updb[o] + sb;
    }
}

// ---------------- tf32 pre-rounding of GEMM inputs ----------------
__global__ void round_conc_k(const float* __restrict__ src){
    size_t i = (size_t)blockIdx.x*256 + threadIdx.x;
    ((float4*)g_ct)[i] = f2t4(((const float4*)src)[i]);
}
__global__ void round_w_k(const float* __restrict__ src){
    size_t i = (size_t)blockIdx.x*256 + threadIdx.x;
    ((float4*)g_wt)[i] = f2t4(((const float4*)src)[i]);
}

// ---------------- adjacency aggregation (writes tf32-rounded) ----------------
__global__ void __launch_bounds__(256) agg_k(int sel){
    const float* __restrict__ src = sel ? g_ns1 : g_ns0;
    int idx = blockIdx.x*256 + threadIdx.x;           // over NB*64
    int b = idx >> 6, h4 = (idx & 63) << 2;
    const float* base = src + (size_t)b*NSD + h4;
    float4 v[9];
    #pragma unroll
    for (int j = 0; j < 9; j++) v[j] = *(const float4*)(base + j*HID);
    float4 sall = v[0];
    #pragma unroll
    for (int j = 1; j < 9; j++) sall = f4add(sall, v[j]);
    float* ob = g_agg + (size_t)b*NSD + h4;
    *(float4*)(ob + 0*HID) = f2t4(f4scale(sall, 1.f/9.f));
    *(float4*)(ob + 1*HID) = f2t4(f4scale(f4add(v[0], v[1]), 0.5f));
    float4 b06 = f4add(v[0], f4add(v[7], v[8]));
    #pragma unroll
    for (int i = 2; i <= 6; i++)
        *(float4*)(ob + i*HID) = f2t4(f4scale(f4add(b06, v[i]), 0.25f));
    float4 r78 = f2t4(f4scale(f4sub(sall, v[1]), 0.125f));
    *(float4*)(ob + 7*HID) = r78;
    *(float4*)(ob + 8*HID) = r78;
}

// ---------------- tf32 mma.sync GEMM ----------------
// CTA tile 128(M) x 128(N), K chunks of 32. 8 warps (2x4), warp tile 64x32.
// 3-stage cp.async ring, ldmatrix.x4 fragment loads, fused epilogue.
// 2 CTAs/SM (110.6 KB smem) so pipeline stalls overlap across CTAs.
// MODE 0: g_ct[16384,2048] @ g_wt[2304,2048]^T + init epilogue -> g_ns0
// MODE 1: [ns|agg][147456,512] @ g_wc[256,512]^T, tanh epilogue -> ns ping-pong
#define PADROW 144                 // 36 floats per 32-float k-row (LDSM conflict-free)
#define AS_BYTES (128*PADROW)      // 18432
#define STAGE_BYTES (2*AS_BYTES)   // 36864 (A | B)
template<int MODE>
__global__ void __launch_bounds__(256, 2) gemm_k(
    const float* __restrict__ f2nb, const float* __restrict__ logits,
    const float* __restrict__ encw, const float* __restrict__ encb,
    int sel)
{
    constexpr int KB = (MODE==0) ? FDIM : 512;
    constexpr int NC = KB / 32;

    extern __shared__ char smem_raw[];
    const uint32_t sbase = smem_u32(smem_raw);

    const int tid = threadIdx.x, wid = tid >> 5, lane = tid & 31;
    const int row0 = blockIdx.y * 128, col0 = blockIdx.x * 128;

    // ---- global load mapping: A and B each 128 rows, 2 threads/row, 4x16B each ----
    const int lrow = tid >> 1, lseg0 = (tid & 1) * 4;
    const uint32_t adst0 = (uint32_t)lrow*PADROW + (uint32_t)lseg0*16;
    const uint32_t bdst0 = AS_BYTES + adst0;

    const float* agp; const float* agp2 = nullptr; const float* bgp;
    if constexpr (MODE == 0){
        agp = g_ct + (size_t)(row0 + lrow)*FDIM + lseg0*4;
        bgp = g_wt + (size_t)(col0 + lrow)*FDIM + lseg0*4;
    } else {
        int r = row0 + lrow, b = r / 9, n = r - 9*b;
        size_t base = (size_t)b*NSD + n*HID + lseg0*4;
        agp  = (sel ? g_ns1 : g_ns0) + base;
        agp2 = g_agg + base;
        bgp  = g_wc + (size_t)(col0 + lrow)*KB + lseg0*4;
    }

    auto load_stage = [&](int s, int c){
        const uint32_t sb = sbase + (uint32_t)s*STAGE_BYTES;
        const float* ap;
        if constexpr (MODE == 0) ap = agp + c*32;
        else                     ap = ((c < 8) ? agp : agp2) + (c & 7)*32;
        const float* bp = bgp + c*32;
        #pragma unroll
        for (int j = 0; j < 4; j++) CP16(sb + adst0 + j*16, ap + 4*j);
        #pragma unroll
        for (int j = 0; j < 4; j++) CP16(sb + bdst0 + j*16, bp + 4*j);
        CP_COMMIT();
    };

    // ---- fragment (ldmatrix) address setup ----
    const int mb = (wid & 1) * 64, nb = (wid >> 1) * 32;
    const int sub = lane >> 3;
    const int lrf = (sub & 1)*8 + (lane & 7);      // A: row within 16-row tile
    const int lca = (sub >> 1) * 16;               // A: 16B chunk (k 0-3 / 4-7)
    uint32_t aoff[4];
    #pragma unroll
    for (int fm = 0; fm < 4; fm++)
        aoff[fm] = (uint32_t)(mb + fm*16 + lrf)*PADROW + lca;
    const int brf = (sub >> 1)*8 + (lane & 7);     // B: row within 16-row pair
    const int lcb = (sub & 1) * 16;
    uint32_t boff[2];
    #pragma unroll
    for (int p = 0; p < 2; p++)
        boff[p] = AS_BYTES + (uint32_t)(nb + p*16 + brf)*PADROW + lcb;

    float acc[4][4][4];
    #pragma unroll
    for (int i=0;i<4;i++)
        #pragma unroll
        for (int j=0;j<4;j++)
            #pragma unroll
            for (int e=0;e<4;e++) acc[i][j][e] = 0.f;

    // ---- prologue: 2 stages in flight ----
    load_stage(0, 0);
    load_stage(1, 1);

    // ---- main loop ----
    for (int c = 0; c < NC; c++){
        CP_WAIT1();                 // chunk c landed
        __syncthreads();            // stage (c+2)%3 is free (all warps past it)
        if (c + 2 < NC) load_stage((c + 2) % 3, c + 2);
        else            CP_COMMIT();

        const uint32_t stg = sbase + (uint32_t)(c % 3)*STAGE_BYTES;
        #pragma unroll
        for (int ks = 0; ks < 4; ks++){
            uint32_t a[4][4], b[4][2];
            #pragma unroll
            for (int fm = 0; fm < 4; fm++)
                LDSM4(a[fm][0], a[fm][1], a[fm][2], a[fm][3], stg + aoff[fm] + ks*32);
            #pragma unroll
            for (int p = 0; p < 2; p++)
                LDSM4(b[2*p][0], b[2*p][1], b[2*p+1][0], b[2*p+1][1], stg + boff[p] + ks*32);
            #pragma unroll
            for (int fm = 0; fm < 4; fm++)
                #pragma unroll
                for (int fn = 0; fn < 4; fn++)
                    mma8(acc[fm][fn], a[fm], b[fn][0], b[fn][1]);
        }
    }

    // ---- fused epilogue (register accumulators) ----
    const int g = lane >> 2, tg = lane & 3;
    #pragma unroll
    for (int fm = 0; fm < 4; fm++){
        const int gm = row0 + mb + fm*16 + g;
        size_t cb0, cb1;
        float lg0 = 0.f, lg1 = 0.f;
        if constexpr (MODE == 0){
            const int node = col0 >> 8;            // 128-col tile lies in one node
            lg0 = logits[gm*9 + node];
            lg1 = logits[(gm+8)*9 + node];
            cb0 = (size_t)gm * NSD;
            cb1 = (size_t)(gm + 8) * NSD;
        } else {
            const int g2 = gm + 8;
            cb0 = (size_t)(gm/9)*NSD + (gm%9)*HID;
            cb1 = (size_t)(g2/9)*NSD + (g2%9)*HID;
        }
        float* dst0; float* dst1;
        if constexpr (MODE == 0){ dst0 = g_ns0 + cb0; dst1 = g_ns0 + cb1; }
        else { float* d = sel ? g_ns0 : g_ns1; dst0 = d + cb0; dst1 = d + cb1; }

        #pragma unroll
        for (int fn = 0; fn < 4; fn++){
            const int gn = col0 + nb + fn*8 + 2*tg;
            float2 v0, v1;
            if constexpr (MODE == 0){
                const int h = gn & 255;
                const float a0 = f2nb[gn]   + encb[h];
                const float a1 = f2nb[gn+1] + encb[h+1];
                const float e0 = encw[h], e1 = encw[h+1];
                v0.x = f2t(acc[fm][fn][0] + a0 + lg0*e0);
                v0.y = f2t(acc[fm][fn][1] + a1 + lg0*e1);
                v1.x = f2t(acc[fm][fn][2] + a0 + lg1*e0);
                v1.y = f2t(acc[fm][fn][3] + a1 + lg1*e1);
            } else {
                const float b0 = g_bc[gn], b1 = g_bc[gn+1];
                v0.x = f2t(tanhf(acc[fm][fn][0] + b0));
                v0.y = f2t(tanhf(acc[fm][fn][1] + b1));
                v1.x = f2t(tanhf(acc[fm][fn][2] + b0));
                v1.y = f2t(tanhf(acc[fm][fn][3] + b1));
            }
            *(float2*)(dst0 + gn) = v0;
            *(float2*)(dst1 + gn) = v1;
        }
    }
}

// ---------------- output heads ----------------
__global__ void __launch_bounds__(256) out_k(const float* __restrict__ outw,
                                             const float* __restrict__ outb,
                                             float* __restrict__ out){
    int wid = threadIdx.x >> 5, lane = threadIdx.x & 31;
    int b = blockIdx.x * 8 + wid;
    const float* r7 = g_ns0 + (size_t)b*NSD + 7*HID;
    float s7 = 0.f, s8 = 0.f;
    #pragma unroll
    for (int i = lane; i < HID; i += 32){
        float w = outw[i];
        s7 += r7[i] * w;
        s8 += r7[i + HID] * w;
    }
    #pragma unroll
    for (int o = 16; o > 0; o >>= 1){
        s7 += __shfl_xor_sync(0xffffffffu, s7, o);
        s8 += __shfl_xor_sync(0xffffffffu, s8, o);
    }
    if (lane == 0){
        out[b]      = s7 + outb[0];
        out[NB + b] = s8 + outb[0];
    }
}

// ---------------- launch ----------------
extern "C" void kernel_launch(void* const* d_in, const int* in_sizes, int n_in,
                              void* d_out, int out_size){
    const float* conc   = (const float*)d_in[0];
    const float* logits = (const float*)d_in[1];
    const float* encw   = (const float*)d_in[2];
    const float* encb   = (const float*)d_in[3];
    const float* f2nw   = (const float*)d_in[4];
    const float* f2nb   = (const float*)d_in[5];
    const float* msgw   = (const float*)d_in[6];
    const float* msgb   = (const float*)d_in[7];
    const float* updw   = (const float*)d_in[8];
    const float* updb   = (const float*)d_in[9];
    const float* outw   = (const float*)d_in[10];
    const float* outb   = (const float*)d_in[11];
    float* out = (float*)d_out;

    const int SMEM_BYTES = 3 * STAGE_BYTES;   // 110592 -> 2 CTAs/SM
    cudaFuncSetAttribute(gemm_k<0>, cudaFuncAttributeMaxDynamicSharedMemorySize, SMEM_BYTES);
    cudaFuncSetAttribute(gemm_k<1>, cudaFuncAttributeMaxDynamicSharedMemorySize, SMEM_BYTES);

    prep_k<<<256, 256>>>(msgw, msgb, updw, updb);
    round_conc_k<<<(NB*(FDIM/4))/256, 256>>>(conc);
    round_w_k<<<(NSD*(FDIM/4))/256, 256>>>(f2nw);

    // init: node_states -> g_ns0
    gemm_k<0><<<dim3(NSD/128, NB/128), 256, SMEM_BYTES>>>(f2nb, logits, encw, encb, 0);

    // 4 message-passing steps (folded single-GEMM form, ping-pong ns0/ns1)
    for (int s = 0; s < 4; s++){
        agg_k<<<(NB*64)/256, 256>>>(s & 1);
        gemm_k<1><<<dim3(2, (NB*NODES)/128), 256, SMEM_BYTES>>>(nullptr, nullptr,
                                                                nullptr, nullptr, s & 1);
    }

    out_k<<<NB/8, 256>>>(outw, outb, out);
}

// round 9
// speedup vs baseline: 1.1275x; 1.0004x over previous
#include <cuda_runtime.h>
#include <stdint.h>

#define NB   16384
#define FDIM 2048
#define HID  256
#define NODES 9
#define NSD  2304   // 9*256

// ---------------- static scratch ----------------
__device__ float g_ns0[(size_t)NB * NSD];
__device__ float g_ns1[(size_t)NB * NSD];
__device__ float g_agg[(size_t)NB * NSD];
__device__ float g_ct [(size_t)NB * FDIM];   // tf32-rounded conc
__device__ float g_wt [(size_t)NSD * FDIM];  // tf32-rounded f2n_w
__device__ float g_wc [HID * 512];           // folded step weight (tf32-rounded)
__device__ float g_bc [HID];                 // folded step bias (fp32)

// ---------------- helpers ----------------
__device__ __forceinline__ float f2t(float x){
    uint32_t u; asm("cvt.rna.tf32.f32 %0, %1;" : "=r"(u) : "f"(x));
    return __uint_as_float(u);
}
__device__ __forceinline__ float4 f2t4(float4 v){
    v.x=f2t(v.x); v.y=f2t(v.y); v.z=f2t(v.z); v.w=f2t(v.w); return v;
}
__device__ __forceinline__ float4 f4add(float4 a, float4 b){
    a.x+=b.x; a.y+=b.y; a.z+=b.z; a.w+=b.w; return a;
}
__device__ __forceinline__ float4 f4sub(float4 a, float4 b){
    a.x-=b.x; a.y-=b.y; a.z-=b.z; a.w-=b.w; return a;
}
__device__ __forceinline__ float4 f4scale(float4 a, float s){
    a.x*=s; a.y*=s; a.z*=s; a.w*=s; return a;
}
__device__ __forceinline__ uint32_t smem_u32(const void* p){
    uint32_t a;
    asm("{ .reg .u64 t; cvta.to.shared.u64 t, %1; cvt.u32.u64 %0, t; }" : "=r"(a) : "l"(p));
    return a;
}
__device__ __forceinline__ void mma8(float c[4], const uint32_t a[4], uint32_t b0, uint32_t b1){
    asm volatile(
        "mma.sync.aligned.m16n8k8.row.col.f32.tf32.tf32.f32 "
        "{%0,%1,%2,%3},{%4,%5,%6,%7},{%8,%9},{%0,%1,%2,%3};\n"
        : "+f"(c[0]),"+f"(c[1]),"+f"(c[2]),"+f"(c[3])
        : "r"(a[0]),"r"(a[1]),"r"(a[2]),"r"(a[3]),"r"(b0),"r"(b1));
}
#define LDSM4(r0,r1,r2,r3,addr) \
    asm volatile("ldmatrix.sync.aligned.m8n8.x4.shared.b16 {%0,%1,%2,%3}, [%4];" \
        : "=r"(r0),"=r"(r1),"=r"(r2),"=r"(r3) : "r"(addr))

#define CP16(dst, src) asm volatile("cp.async.cg.shared.global [%0], [%1], 16;\n" :: "r"(dst), "l"(src))
#define CP_COMMIT()    asm volatile("cp.async.commit_group;\n" ::: "memory")
#define CP_WAIT1()     asm volatile("cp.async.wait_group 1;\n" ::: "memory")

// ---------------- weight folding ----------------
__global__ void prep_k(const float* __restrict__ msgw, const float* __restrict__ msgb,
                       const float* __restrict__ updw, const float* __restrict__ updb){
    int o = blockIdx.x, t = threadIdx.x;
    __shared__ float u2[HID];
    u2[t] = updw[o*512 + 256 + t];
    __syncthreads();
    g_wc[o*512 + t] = f2t(updw[o*512 + t]);
    float s = 0.f;
    #pragma unroll 8
    for (int j = 0; j < HID; j++) s += u2[j] * msgw[j*HID + t];
    g_wc[o*512 + 256 + t] = f2t(s);
    if (t == 0){
        float sb = 0.f;
        for (int j = 0; j < HID; j++) sb += u2[j] * msgb[j];
        g_bc[o] = updb[o] + sb;
    }
}

// ---------------- tf32 pre-rounding of GEMM inputs ----------------
__global__ void round_conc_k(const float* __restrict__ src){
    size_t i = (size_t)blockIdx.x*256 + threadIdx.x;
    ((float4*)g_ct)[i] = f2t4(((const float4*)src)[i]);
}
__global__ void round_w_k(const float* __restrict__ src){
    size_t i = (size_t)blockIdx.x*256 + threadIdx.x;
    ((float4*)g_wt)[i] = f2t4(((const float4*)src)[i]);
}

// ---------------- adjacency aggregation (writes tf32-rounded) ----------------
__global__ void __launch_bounds__(256) agg_k(int sel){
    const float* __restrict__ src = sel ? g_ns1 : g_ns0;
    int idx = blockIdx.x*256 + threadIdx.x;           // over NB*64
    int b = idx >> 6, h4 = (idx & 63) << 2;
    const float* base = src + (size_t)b*NSD + h4;
    float4 v[9];
    #pragma unroll
    for (int j = 0; j < 9; j++) v[j] = *(const float4*)(base + j*HID);
    float4 sall = v[0];
    #pragma unroll
    for (int j = 1; j < 9; j++) sall = f4add(sall, v[j]);
    float* ob = g_agg + (size_t)b*NSD + h4;
    *(float4*)(ob + 0*HID) = f2t4(f4scale(sall, 1.f/9.f));
    *(float4*)(ob + 1*HID) = f2t4(f4scale(f4add(v[0], v[1]), 0.5f));
    float4 b06 = f4add(v[0], f4add(v[7], v[8]));
    #pragma unroll
    for (int i = 2; i <= 6; i++)
        *(float4*)(ob + i*HID) = f2t4(f4scale(f4add(b06, v[i]), 0.25f));
    float4 r78 = f2t4(f4scale(f4sub(sall, v[1]), 0.125f));
    *(float4*)(ob + 7*HID) = r78;
    *(float4*)(ob + 8*HID) = r78;
}

// ---------------- tf32 mma.sync GEMM ----------------
// CTA tile 128(M) x 128(N), K chunks of 32. 8 warps (2x4), warp tile 64x32.
// 3-stage cp.async ring, ldmatrix.x4 fragment loads, fused epilogue.
// 2 CTAs/SM (110.6 KB smem) so pipeline stalls overlap across CTAs.
// MODE 0: g_ct[16384,2048] @ g_wt[2304,2048]^T + init epilogue -> g_ns0
// MODE 1: [ns|agg][147456,512] @ g_wc[256,512]^T, tanh epilogue -> ns ping-pong
#define PADROW 144                 // 36 floats per 32-float k-row (LDSM conflict-free)
#define AS_BYTES (128*PADROW)      // 18432
#define STAGE_BYTES (2*AS_BYTES)   // 36864 (A | B)
template<int MODE>
__global__ void __launch_bounds__(256, 2) gemm_k(
    const float* __restrict__ f2nb, const float* __restrict__ logits,
    const float* __restrict__ encw, const float* __restrict__ encb,
    int sel)
{
    constexpr int KB = (MODE==0) ? FDIM : 512;
    constexpr int NC = KB / 32;

    extern __shared__ char smem_raw[];
    const uint32_t sbase = smem_u32(smem_raw);

    const int tid = threadIdx.x, wid = tid >> 5, lane = tid & 31;
    const int row0 = blockIdx.y * 128, col0 = blockIdx.x * 128;

    // ---- global load mapping: A and B each 128 rows, 2 threads/row, 4x16B each ----
    const int lrow = tid >> 1, lseg0 = (tid & 1) * 4;
    const uint32_t adst0 = (uint32_t)lrow*PADROW + (uint32_t)lseg0*16;
    const uint32_t bdst0 = AS_BYTES + adst0;

    const float* agp; const float* agp2 = nullptr; const float* bgp;
    if constexpr (MODE == 0){
        agp = g_ct + (size_t)(row0 + lrow)*FDIM + lseg0*4;
        bgp = g_wt + (size_t)(col0 + lrow)*FDIM + lseg0*4;
    } else {
        int r = row0 + lrow, b = r / 9, n = r - 9*b;
        size_t base = (size_t)b*NSD + n*HID + lseg0*4;
        agp  = (sel ? g_ns1 : g_ns0) + base;
        agp2 = g_agg + base;
        bgp  = g_wc + (size_t)(col0 + lrow)*KB + lseg0*4;
    }

    auto load_stage = [&](int s, int c){
        const uint32_t sb = sbase + (uint32_t)s*STAGE_BYTES;
        const float* ap;
        if constexpr (MODE == 0) ap = agp + c*32;
        else                     ap = ((c < 8) ? agp : agp2) + (c & 7)*32;
        const float* bp = bgp + c*32;
        #pragma unroll
        for (int j = 0; j < 4; j++) CP16(sb + adst0 + j*16, ap + 4*j);
        #pragma unroll
        for (int j = 0; j < 4; j++) CP16(sb + bdst0 + j*16, bp + 4*j);
        CP_COMMIT();
    };

    // ---- fragment (ldmatrix) address setup ----
    const int mb = (wid & 1) * 64, nb = (wid >> 1) * 32;
    const int sub = lane >> 3;
    const int lrf = (sub & 1)*8 + (lane & 7);      // A: row within 16-row tile
    const int lca = (sub >> 1) * 16;               // A: 16B chunk (k 0-3 / 4-7)
    uint32_t aoff[4];
    #pragma unroll
    for (int fm = 0; fm < 4; fm++)
        aoff[fm] = (uint32_t)(mb + fm*16 + lrf)*PADROW + lca;
    const int brf = (sub >> 1)*8 + (lane & 7);     // B: row within 16-row pair
    const int lcb = (sub & 1) * 16;
    uint32_t boff[2];
    #pragma unroll
    for (int p = 0; p < 2; p++)
        boff[p] = AS_BYTES + (uint32_t)(nb + p*16 + brf)*PADROW + lcb;

    float acc[4][4][4];
    #pragma unroll
    for (int i=0;i<4;i++)
        #pragma unroll
        for (int j=0;j<4;j++)
            #pragma unroll
            for (int e=0;e<4;e++) acc[i][j][e] = 0.f;

    // ---- prologue: 2 stages in flight ----
    load_stage(0, 0);
    load_stage(1, 1);

    // ---- main loop ----
    for (int c = 0; c < NC; c++){
        CP_WAIT1();                 // chunk c landed
        __syncthreads();            // stage (c+2)%3 is free (all warps past it)
        if (c + 2 < NC) load_stage((c + 2) % 3, c + 2);
        else            CP_COMMIT();

        const uint32_t stg = sbase + (uint32_t)(c % 3)*STAGE_BYTES;
        #pragma unroll
        for (int ks = 0; ks < 4; ks++){
            uint32_t a[4][4], b[4][2];
            #pragma unroll
            for (int fm = 0; fm < 4; fm++)
                LDSM4(a[fm][0], a[fm][1], a[fm][2], a[fm][3], stg + aoff[fm] + ks*32);
            #pragma unroll
            for (int p = 0; p < 2; p++)
                LDSM4(b[2*p][0], b[2*p][1], b[2*p+1][0], b[2*p+1][1], stg + boff[p] + ks*32);
            #pragma unroll
            for (int fm = 0; fm < 4; fm++)
                #pragma unroll
                for (int fn = 0; fn < 4; fn++)
                    mma8(acc[fm][fn], a[fm], b[fn][0], b[fn][1]);
        }
    }

    // ---- fused epilogue (register accumulators) ----
    const int g = lane >> 2, tg = lane & 3;
    #pragma unroll
    for (int fm = 0; fm < 4; fm++){
        const int gm = row0 + mb + fm*16 + g;
        size_t cb0, cb1;
        float lg0 = 0.f, lg1 = 0.f;
        if constexpr (MODE == 0){
            const int node = col0 >> 8;            // 128-col tile lies in one node
            lg0 = logits[gm*9 + node];
            lg1 = logits[(gm+8)*9 + node];
            cb0 = (size_t)gm * NSD;
            cb1 = (size_t)(gm + 8) * NSD;
        } else {
            const int g2 = gm + 8;
            cb0 = (size_t)(gm/9)*NSD + (gm%9)*HID;
            cb1 = (size_t)(g2/9)*NSD + (g2%9)*HID;
        }
        float* dst0; float* dst1;
        if constexpr (MODE == 0){ dst0 = g_ns0 + cb0; dst1 = g_ns0 + cb1; }
        else { float* d = sel ? g_ns0 : g_ns1; dst0 = d + cb0; dst1 = d + cb1; }

        #pragma unroll
        for (int fn = 0; fn < 4; fn++){
            const int gn = col0 + nb + fn*8 + 2*tg;
            float2 v0, v1;
            if constexpr (MODE == 0){
                const int h = gn & 255;
                const float a0 = f2nb[gn]   + encb[h];
                const float a1 = f2nb[gn+1] + encb[h+1];
                const float e0 = encw[h], e1 = encw[h+1];
                v0.x = f2t(acc[fm][fn][0] + a0 + lg0*e0);
                v0.y = f2t(acc[fm][fn][1] + a1 + lg0*e1);
                v1.x = f2t(acc[fm][fn][2] + a0 + lg1*e0);
                v1.y = f2t(acc[fm][fn][3] + a1 + lg1*e1);
            } else {
                const float b0 = g_bc[gn], b1 = g_bc[gn+1];
                v0.x = f2t(tanhf(acc[fm][fn][0] + b0));
                v0.y = f2t(tanhf(acc[fm][fn][1] + b1));
                v1.x = f2t(tanhf(acc[fm][fn][2] + b0));
                v1.y = f2t(tanhf(acc[fm][fn][3] + b1));
            }
            *(float2*)(dst0 + gn) = v0;
            *(float2*)(dst1 + gn) = v1;
        }
    }
}

// ---------------- output heads ----------------
__global__ void __launch_bounds__(256) out_k(const float* __restrict__ outw,
                                             const float* __restrict__ outb,
                                             float* __restrict__ out){
    int wid = threadIdx.x >> 5, lane = threadIdx.x & 31;
    int b = blockIdx.x * 8 + wid;
    const float* r7 = g_ns0 + (size_t)b*NSD + 7*HID;
    float s7 = 0.f, s8 = 0.f;
    #pragma unroll
    for (int i = lane; i < HID; i += 32){
        float w = outw[i];
        s7 += r7[i] * w;
        s8 += r7[i + HID] * w;
    }
    #pragma unroll
    for (int o = 16; o > 0; o >>= 1){
        s7 += __shfl_xor_sync(0xffffffffu, s7, o);
        s8 += __shfl_xor_sync(0xffffffffu, s8, o);
    }
    if (lane == 0){
        out[b]      = s7 + outb[0];
        out[NB + b] = s8 + outb[0];
    }
}

// ---------------- launch ----------------
extern "C" void kernel_launch(void* const* d_in, const int* in_sizes, int n_in,
                              void* d_out, int out_size){
    const float* conc   = (const float*)d_in[0];
    const float* logits = (const float*)d_in[1];
    const float* encw   = (const float*)d_in[2];
    const float* encb   = (const float*)d_in[3];
    const float* f2nw   = (const float*)d_in[4];
    const float* f2nb   = (const float*)d_in[5];
    const float* msgw   = (const float*)d_in[6];
    const float* msgb   = (const float*)d_in[7];
    const float* updw   = (const float*)d_in[8];
    const float* updb   = (const float*)d_in[9];
    const float* outw   = (const float*)d_in[10];
    const float* outb   = (const float*)d_in[11];
    float* out = (float*)d_out;

    const int SMEM_BYTES = 3 * STAGE_BYTES;   // 110592 -> 2 CTAs/SM
    cudaFuncSetAttribute(gemm_k<0>, cudaFuncAttributeMaxDynamicSharedMemorySize, SMEM_BYTES);
    cudaFuncSetAttribute(gemm_k<1>, cudaFuncAttributeMaxDynamicSharedMemorySize, SMEM_BYTES);

    prep_k<<<256, 256>>>(msgw, msgb, updw, updb);
    round_conc_k<<<(NB*(FDIM/4))/256, 256>>>(conc);
    round_w_k<<<(NSD*(FDIM/4))/256, 256>>>(f2nw);

    // init: node_states -> g_ns0
    gemm_k<0><<<dim3(NSD/128, NB/128), 256, SMEM_BYTES>>>(f2nb, logits, encw, encb, 0);

    // 4 message-passing steps (folded single-GEMM form, ping-pong ns0/ns1)
    for (int s = 0; s < 4; s++){
        agg_k<<<(NB*64)/256, 256>>>(s & 1);
        gemm_k<1><<<dim3(2, (NB*NODES)/128), 256, SMEM_BYTES>>>(nullptr, nullptr,
                                                                nullptr, nullptr, s & 1);
    }

    out_k<<<NB/8, 256>>>(outw, outb, out);
}